// round 1
// baseline (speedup 1.0000x reference)
#include <cuda_runtime.h>

// ValueNorm: one-shot Welford batch update (Chan merge) + normalize.
// HBM-bound: 2 reads + 1 write of 256MB. Three kernels, all graph-capturable,
// no device allocation (partials live in __device__ globals).

#define RED_BLOCKS 2368   // 148 SMs * 16
#define RED_THREADS 256
#define EPS 1e-5

__device__ double g_psum[RED_BLOCKS];
__device__ double g_psq[RED_BLOCKS];
__device__ float  g_shift;   // new_mean
__device__ float  g_scale;   // 1/std

// ---------------------------------------------------------------------------
// Kernel 1: per-block partial sum / sum-of-squares.
// ---------------------------------------------------------------------------
__global__ void __launch_bounds__(RED_THREADS)
vn_reduce_kernel(const float* __restrict__ x, long long n)
{
    long long n4 = n >> 2;
    const float4* __restrict__ x4 = (const float4*)x;

    float s = 0.0f, q = 0.0f;
    long long idx    = (long long)blockIdx.x * blockDim.x + threadIdx.x;
    long long stride = (long long)gridDim.x * blockDim.x;

    for (long long i = idx; i < n4; i += stride) {
        float4 v = x4[i];
        s += v.x + v.y + v.z + v.w;
        q += v.x * v.x + v.y * v.y + v.z * v.z + v.w * v.w;
    }
    // scalar tail (n not divisible by 4) — handled by low global threads
    long long tail_base = n4 << 2;
    long long rem = n - tail_base;
    if (idx < rem) {
        float v = x[tail_base + idx];
        s += v;
        q += v * v;
    }

    // block reduce in double
    double ds = (double)s, dq = (double)q;
    #pragma unroll
    for (int o = 16; o > 0; o >>= 1) {
        ds += __shfl_down_sync(0xFFFFFFFFu, ds, o);
        dq += __shfl_down_sync(0xFFFFFFFFu, dq, o);
    }
    __shared__ double sh_s[RED_THREADS / 32];
    __shared__ double sh_q[RED_THREADS / 32];
    int wid = threadIdx.x >> 5;
    int lid = threadIdx.x & 31;
    if (lid == 0) { sh_s[wid] = ds; sh_q[wid] = dq; }
    __syncthreads();
    if (threadIdx.x == 0) {
        double ts = 0.0, tq = 0.0;
        #pragma unroll
        for (int w = 0; w < RED_THREADS / 32; ++w) { ts += sh_s[w]; tq += sh_q[w]; }
        g_psum[blockIdx.x] = ts;
        g_psq[blockIdx.x]  = tq;
    }
}

// ---------------------------------------------------------------------------
// Kernel 2: final reduction + Chan merge + scalar outputs.
// ---------------------------------------------------------------------------
__global__ void __launch_bounds__(1024)
vn_finalize_kernel(const float* __restrict__ count_p,
                   const float* __restrict__ mean_p,
                   const float* __restrict__ m2_p,
                   float* __restrict__ out_tail,   // nullptr if no scalar outputs
                   double n)
{
    double s = 0.0, q = 0.0;
    for (int i = threadIdx.x; i < RED_BLOCKS; i += blockDim.x) {
        s += g_psum[i];
        q += g_psq[i];
    }
    #pragma unroll
    for (int o = 16; o > 0; o >>= 1) {
        s += __shfl_down_sync(0xFFFFFFFFu, s, o);
        q += __shfl_down_sync(0xFFFFFFFFu, q, o);
    }
    __shared__ double sh_s[32];
    __shared__ double sh_q[32];
    int wid = threadIdx.x >> 5;
    int lid = threadIdx.x & 31;
    if (lid == 0) { sh_s[wid] = s; sh_q[wid] = q; }
    __syncthreads();

    if (threadIdx.x == 0) {
        int nwarps = blockDim.x >> 5;
        double ts = 0.0, tq = 0.0;
        for (int w = 0; w < nwarps; ++w) { ts += sh_s[w]; tq += sh_q[w]; }

        double bmean = ts / n;
        double bm2   = tq - ts * ts / n;   // sum((x-bmean)^2)

        double count = (double)*count_p;
        double mean  = (double)*mean_p;
        double m2    = (double)*m2_p;

        double new_count = count + n;
        double delta     = bmean - mean;
        double new_mean  = mean + delta * n / new_count;
        double new_m2    = m2 + bm2 + delta * delta * count * n / new_count;

        double denom = new_count - 1.0;
        if (denom < 1.0) denom = 1.0;
        double var = new_m2 / denom;
        double std = sqrt(var + (double)EPS);

        g_shift = (float)new_mean;
        g_scale = (float)(1.0 / std);

        if (out_tail) {
            out_tail[0] = (float)new_count;
            out_tail[1] = (float)new_mean;
            out_tail[2] = (float)new_m2;
        }
    }
}

// ---------------------------------------------------------------------------
// Kernel 3: normalize y = (x - mean) * (1/std).
// ---------------------------------------------------------------------------
__global__ void __launch_bounds__(RED_THREADS)
vn_normalize_kernel(const float* __restrict__ x, float* __restrict__ y, long long n)
{
    float shift = g_shift;
    float scale = g_scale;

    long long n4 = n >> 2;
    const float4* __restrict__ x4 = (const float4*)x;
    float4* __restrict__ y4 = (float4*)y;

    long long idx    = (long long)blockIdx.x * blockDim.x + threadIdx.x;
    long long stride = (long long)gridDim.x * blockDim.x;

    for (long long i = idx; i < n4; i += stride) {
        float4 v = x4[i];
        v.x = (v.x - shift) * scale;
        v.y = (v.y - shift) * scale;
        v.z = (v.z - shift) * scale;
        v.w = (v.w - shift) * scale;
        y4[i] = v;
    }
    long long tail_base = n4 << 2;
    long long rem = n - tail_base;
    if (idx < rem) {
        float v = x[tail_base + idx];
        y[tail_base + idx] = (v - shift) * scale;
    }
}

// ---------------------------------------------------------------------------
extern "C" void kernel_launch(void* const* d_in, const int* in_sizes, int n_in,
                              void* d_out, int out_size)
{
    const float* x       = (const float*)d_in[0];
    const float* count_p = (const float*)d_in[1];
    const float* mean_p  = (const float*)d_in[2];
    const float* m2_p    = (const float*)d_in[3];
    float* out = (float*)d_out;

    long long n = (long long)in_sizes[0];

    float* out_tail = nullptr;
    if ((long long)out_size >= n + 3) out_tail = out + n;

    vn_reduce_kernel<<<RED_BLOCKS, RED_THREADS>>>(x, n);
    vn_finalize_kernel<<<1, 1024>>>(count_p, mean_p, m2_p, out_tail, (double)n);
    vn_normalize_kernel<<<RED_BLOCKS, RED_THREADS>>>(x, out, n);
}